// round 4
// baseline (speedup 1.0000x reference)
#include <cuda_runtime.h>
#include <math.h>

#define H   1032
#define INW 2064
#define G3  3096
#define SL  8192
#define V   50257

// d_out layout: output(V), attn_context(H), hidden(H), attn_w(S)
#define OUT_CTX    50257
#define OUT_HID    51289
#define OUT_ATTNW  52321

#define NBLK 296        // 2 blocks/SM, one wave

// scratch
__device__ float g_gx[G3];
__device__ float g_gh[G3];
__device__ __align__(16) float g_hnew[H];
__device__ __align__(16) float g_v[H];
__device__ float g_c0;
__device__ float g_scores[SL];
__device__ float g_ctx[H];

__device__ __forceinline__ float dot4(float4 a, float4 b) {
    return a.x * b.x + a.y * b.y + a.z * b.z + a.w * b.w;
}

__device__ __forceinline__ float warp_red(float s) {
    #pragma unroll
    for (int o = 16; o; o >>= 1) s += __shfl_xor_sync(0xffffffffu, s, o);
    return s;
}

// 516 float4 per row: stage ALL 16 loads into registers, then consume.
__device__ __forceinline__ float rowdot516(const float4* __restrict__ w4,
                                           const float4* __restrict__ x4, int lane) {
    float4 r[16];
    #pragma unroll
    for (int i = 0; i < 16; ++i) r[i] = w4[lane + 32 * i];
    float t = 0.f;
    if (lane < 4) t = dot4(w4[512 + lane], x4[512 + lane]);
    float s0 = t, s1 = 0.f, s2 = 0.f, s3 = 0.f;
    #pragma unroll
    for (int i = 0; i < 16; i += 4) {
        s0 += dot4(r[i + 0], x4[lane + 32 * (i + 0)]);
        s1 += dot4(r[i + 1], x4[lane + 32 * (i + 1)]);
        s2 += dot4(r[i + 2], x4[lane + 32 * (i + 2)]);
        s3 += dot4(r[i + 3], x4[lane + 32 * (i + 3)]);
    }
    return (s0 + s1) + (s2 + s3);
}

// 258 float4 per row: stage all 8 loads.
__device__ __forceinline__ float rowdot258(const float4* __restrict__ w4,
                                           const float4* __restrict__ x4, int lane) {
    float4 r[8];
    #pragma unroll
    for (int i = 0; i < 8; ++i) r[i] = w4[lane + 32 * i];
    float t = 0.f;
    if (lane < 2) t = dot4(w4[256 + lane], x4[256 + lane]);
    float s0 = t, s1 = 0.f, s2 = 0.f, s3 = 0.f;
    #pragma unroll
    for (int i = 0; i < 8; i += 4) {
        s0 += dot4(r[i + 0], x4[lane + 32 * (i + 0)]);
        s1 += dot4(r[i + 1], x4[lane + 32 * (i + 1)]);
        s2 += dot4(r[i + 2], x4[lane + 32 * (i + 2)]);
        s3 += dot4(r[i + 3], x4[lane + 32 * (i + 3)]);
    }
    return (s0 + s1) + (s2 + s3);
}

// ---------------- K1: gates. Blocks [0,148): gx rows (W_ih); [148,296): gh rows (W_hh).
__global__ __launch_bounds__(256, 1) void k_gates(
        const int* __restrict__ word, const float* __restrict__ lctx,
        const float* __restrict__ hprev, const float* __restrict__ emb,
        const float* __restrict__ W_ih, const float* __restrict__ W_hh,
        const float* __restrict__ b_ih, const float* __restrict__ b_hh) {
    __shared__ __align__(16) float sx[INW];
    int tid = threadIdx.x, lane = tid & 31, wib = tid >> 5;
    if (blockIdx.x < 148) {
        const float* erow = emb + (size_t)word[0] * H;
        for (int i = tid; i < INW; i += 256) sx[i] = (i < H) ? erow[i] : lctx[i - H];
        __syncthreads();
        for (int row = blockIdx.x * 8 + wib; row < G3; row += 148 * 8) {
            float s = rowdot516((const float4*)(W_ih + (size_t)row * INW),
                                (const float4*)sx, lane);
            s = warp_red(s);
            if (lane == 0) g_gx[row] = s + b_ih[row];
        }
    } else {
        for (int i = tid; i < H; i += 256) sx[i] = hprev[i];
        __syncthreads();
        for (int row = (blockIdx.x - 148) * 8 + wib; row < G3; row += 148 * 8) {
            float s = rowdot258((const float4*)(W_hh + (size_t)row * H),
                                (const float4*)sx, lane);
            s = warp_red(s);
            if (lane == 0) g_gh[row] = s + b_hh[row];
        }
    }
}

// ---------------- K2: GRU combine -> h_new; zero accumulators; c0 = b_a . h_new
__global__ void k_gru(const float* __restrict__ hprev, const float* __restrict__ b_a,
                      float* __restrict__ d_out) {
    __shared__ float acc;
    int tid = threadIdx.x;
    if (tid == 0) acc = 0.f;
    __syncthreads();
    float part = 0.f;
    for (int i = tid; i < H; i += blockDim.x) {
        float r = 1.f / (1.f + expf(-(g_gx[i] + g_gh[i])));
        float z = 1.f / (1.f + expf(-(g_gx[i + H] + g_gh[i + H])));
        float n = tanhf(g_gx[i + 2 * H] + r * g_gh[i + 2 * H]);
        float h = hprev[i];
        float hn = (1.f - z) * n + z * h;
        g_hnew[i] = hn;
        d_out[OUT_HID + i] = hn;
        g_v[i] = 0.f;
        g_ctx[i] = 0.f;
        part += b_a[i] * hn;
    }
    part = warp_red(part);
    if ((tid & 31) == 0) atomicAdd(&acc, part);
    __syncthreads();
    if (tid == 0) g_c0 = acc;
}

// ---------------- K3: v = W_a^T h_new
__global__ void k_va(const float* __restrict__ W_a) {
    int k = blockIdx.x * 128 + threadIdx.x;
    int j0 = blockIdx.y * 129;
    if (k >= H) return;
    float p0 = 0.f, p1 = 0.f, p2 = 0.f;
    int j = j0;
    #pragma unroll 3
    for (int u = 0; u < 43; ++u, j += 3) {
        p0 += W_a[(size_t)(j + 0) * H + k] * g_hnew[j + 0];
        p1 += W_a[(size_t)(j + 1) * H + k] * g_hnew[j + 1];
        p2 += W_a[(size_t)(j + 2) * H + k] * g_hnew[j + 2];
    }
    atomicAdd(&g_v[k], p0 + p1 + p2);
}

// ---------------- K4: scores[s] = enc[s] . v + c0   (persistent, staged loads)
__global__ __launch_bounds__(256, 1) void k_scores(const float* __restrict__ enc) {
    __shared__ __align__(16) float sv[H];
    int tid = threadIdx.x, lane = tid & 31, wib = tid >> 5;
    for (int i = tid; i < H; i += 256) sv[i] = g_v[i];
    __syncthreads();
    for (int row = blockIdx.x * 8 + wib; row < SL; row += NBLK * 8) {
        float s = rowdot258((const float4*)(enc + (size_t)row * H),
                            (const float4*)sv, lane);
        s = warp_red(s);
        if (lane == 0) g_scores[row] = s + g_c0;
    }
}

// ---------------- K5: context (softmax fused; block 0 emits attn_w)
__global__ void k_context(const float* __restrict__ enc, float* __restrict__ d_out) {
    __shared__ float red[8];
    __shared__ float s_m, s_inv;
    __shared__ float sw[64];
    int tid = threadIdx.x, lane = tid & 31, wid = tid >> 5;   // 256 threads, 8 warps

    // block-local softmax stats over all 8192 scores (L2-hot, 32KB)
    float v[32];
    float m = -1e30f;
    #pragma unroll
    for (int u = 0; u < 32; ++u) { v[u] = g_scores[u * 256 + tid]; m = fmaxf(m, v[u]); }
    #pragma unroll
    for (int o = 16; o; o >>= 1) m = fmaxf(m, __shfl_xor_sync(0xffffffffu, m, o));
    if (lane == 0) red[wid] = m;
    __syncthreads();
    if (tid == 0) {
        float t = red[0];
        #pragma unroll
        for (int i = 1; i < 8; ++i) t = fmaxf(t, red[i]);
        s_m = t;
    }
    __syncthreads();
    m = s_m;
    float sum = 0.f;
    #pragma unroll
    for (int u = 0; u < 32; ++u) { v[u] = expf(v[u] - m); sum += v[u]; }
    sum = warp_red(sum);
    if (lane == 0) red[wid] = sum;
    __syncthreads();
    if (tid == 0) {
        float t = 0.f;
        #pragma unroll
        for (int i = 0; i < 8; ++i) t += red[i];
        s_inv = 1.f / t;
    }
    __syncthreads();
    float inv = s_inv;

    if (blockIdx.x == 0) {
        #pragma unroll
        for (int u = 0; u < 32; ++u) d_out[OUT_ATTNW + u * 256 + tid] = v[u] * inv;
    }

    // weights for this block's 64 rows
    int s0 = blockIdx.x * 64;
    if (tid < 64) sw[tid] = expf(g_scores[s0 + tid] - m) * inv;
    __syncthreads();

    float a0 = 0, a1 = 0, a2 = 0, a3 = 0, a4 = 0;
    for (int s = 0; s < 64; ++s) {
        float w = sw[s];
        const float* row = enc + (size_t)(s0 + s) * H;
        a0 += w * row[tid];
        a1 += w * row[tid + 256];
        a2 += w * row[tid + 512];
        a3 += w * row[tid + 768];
        if (tid < 8) a4 += w * row[tid + 1024];
    }
    atomicAdd(&g_ctx[tid], a0);
    atomicAdd(&g_ctx[tid + 256], a1);
    atomicAdd(&g_ctx[tid + 512], a2);
    atomicAdd(&g_ctx[tid + 768], a3);
    if (tid < 8) atomicAdd(&g_ctx[tid + 1024], a4);
}

// ---------------- K6: logits = W_out @ [h_new, ctx] + b_out (persistent, staged; join fused)
__global__ __launch_bounds__(256, 1) void k_out(const float* __restrict__ W_out,
                                                const float* __restrict__ b_out,
                                                float* __restrict__ d_out) {
    __shared__ __align__(16) float sj[INW];
    int tid = threadIdx.x, lane = tid & 31, wib = tid >> 5;
    for (int i = tid; i < H; i += 256) {
        sj[i] = g_hnew[i];
        float c = g_ctx[i];
        sj[H + i] = c;
        if (blockIdx.x == 0) d_out[OUT_CTX + i] = c;
    }
    __syncthreads();
    for (int row = blockIdx.x * 8 + wib; row < V; row += NBLK * 8) {
        float s = rowdot516((const float4*)(W_out + (size_t)row * INW),
                            (const float4*)sj, lane);
        s = warp_red(s);
        if (lane == 0) d_out[row] = s + b_out[row];
    }
}

// ---------------- K7: log-softmax in place (single block; logits L2-hot)
__global__ void k_lsefinal(float* __restrict__ d_out) {
    __shared__ float red[32];
    __shared__ float s_lse;
    int tid = threadIdx.x;                    // 1024
    float m = -1e30f;
    for (int i = tid; i < V; i += 1024) m = fmaxf(m, d_out[i]);
    #pragma unroll
    for (int o = 16; o; o >>= 1) m = fmaxf(m, __shfl_xor_sync(0xffffffffu, m, o));
    if ((tid & 31) == 0) red[tid >> 5] = m;
    __syncthreads();
    if (tid < 32) {
        float t = red[tid];
        #pragma unroll
        for (int o = 16; o; o >>= 1) t = fmaxf(t, __shfl_xor_sync(0xffffffffu, t, o));
        if (tid == 0) red[0] = t;
    }
    __syncthreads();
    m = red[0];
    __syncthreads();
    float sum = 0.f;
    for (int i = tid; i < V; i += 1024) sum += expf(d_out[i] - m);
    sum = warp_red(sum);
    if ((tid & 31) == 0) red[tid >> 5] = sum;
    __syncthreads();
    if (tid < 32) {
        float t = red[tid];
        t = warp_red(t);
        if (tid == 0) s_lse = m + logf(t);
    }
    __syncthreads();
    float lse = s_lse;
    for (int i = tid; i < V; i += 1024) d_out[i] -= lse;
}

extern "C" void kernel_launch(void* const* d_in, const int* in_sizes, int n_in,
                              void* d_out, int out_size) {
    const int*   word  = (const int*)  d_in[0];
    const float* lctx  = (const float*)d_in[1];
    const float* hprev = (const float*)d_in[2];
    const float* enc   = (const float*)d_in[3];
    const float* emb   = (const float*)d_in[4];
    const float* W_ih  = (const float*)d_in[5];
    const float* W_hh  = (const float*)d_in[6];
    const float* b_ih  = (const float*)d_in[7];
    const float* b_hh  = (const float*)d_in[8];
    const float* W_a   = (const float*)d_in[9];
    const float* b_a   = (const float*)d_in[10];
    const float* W_out = (const float*)d_in[11];
    const float* b_out = (const float*)d_in[12];
    float* out = (float*)d_out;

    k_gates   <<<NBLK, 256>>>(word, lctx, hprev, emb, W_ih, W_hh, b_ih, b_hh);
    k_gru     <<<1, 1024>>>(hprev, b_a, out);
    k_va      <<<dim3(9, 8), 128>>>(W_a);
    k_scores  <<<NBLK, 256>>>(enc);
    k_context <<<128, 256>>>(enc, out);
    k_out     <<<NBLK, 256>>>(W_out, b_out, out);
    k_lsefinal<<<1, 1024>>>(out);
}

// round 12
// speedup vs baseline: 1.0801x; 1.0801x over previous
#include <cuda_runtime.h>
#include <cuda_pipeline.h>
#include <math.h>

#define H   1032
#define INW 2064
#define G3  3096
#define SL  8192
#define V   50257

// d_out layout: output(V), attn_context(H), hidden(H), attn_w(S)
#define OUT_CTX    50257
#define OUT_HID    51289
#define OUT_ATTNW  52321

// scratch
__device__ float g_gx[G3];
__device__ float g_gh[G3];
__device__ __align__(16) float g_hnew[H];
__device__ __align__(16) float g_v[H];
__device__ float g_c0;
__device__ float g_scores[SL];
__device__ float g_ctx[H];

__device__ __forceinline__ float dot4(float4 a, float4 b) {
    return a.x * b.x + a.y * b.y + a.z * b.z + a.w * b.w;
}

__device__ __forceinline__ float warp_red(float s) {
    #pragma unroll
    for (int o = 16; o; o >>= 1) s += __shfl_xor_sync(0xffffffffu, s, o);
    return s;
}

// ---- R2-style row dots (for the small LDG kernels) ----
__device__ __forceinline__ float row_dot_516(const float4* __restrict__ w4,
                                             const float4* __restrict__ x4, int lane) {
    float s0 = 0.f, s1 = 0.f, s2 = 0.f, s3 = 0.f;
    #pragma unroll
    for (int i = 0; i < 16; i += 4) {
        float4 a = w4[lane + 32 * (i + 0)];
        float4 b = w4[lane + 32 * (i + 1)];
        float4 c = w4[lane + 32 * (i + 2)];
        float4 d = w4[lane + 32 * (i + 3)];
        s0 += dot4(a, x4[lane + 32 * (i + 0)]);
        s1 += dot4(b, x4[lane + 32 * (i + 1)]);
        s2 += dot4(c, x4[lane + 32 * (i + 2)]);
        s3 += dot4(d, x4[lane + 32 * (i + 3)]);
    }
    if (lane < 4) s0 += dot4(w4[512 + lane], x4[512 + lane]);
    return (s0 + s1) + (s2 + s3);
}

__device__ __forceinline__ float row_dot_258(const float4* __restrict__ w4,
                                             const float4* __restrict__ x4, int lane) {
    float s0 = 0.f, s1 = 0.f, s2 = 0.f, s3 = 0.f;
    #pragma unroll
    for (int i = 0; i < 8; i += 4) {
        float4 a = w4[lane + 32 * (i + 0)];
        float4 b = w4[lane + 32 * (i + 1)];
        float4 c = w4[lane + 32 * (i + 2)];
        float4 d = w4[lane + 32 * (i + 3)];
        s0 += dot4(a, x4[lane + 32 * (i + 0)]);
        s1 += dot4(b, x4[lane + 32 * (i + 1)]);
        s2 += dot4(c, x4[lane + 32 * (i + 2)]);
        s3 += dot4(d, x4[lane + 32 * (i + 3)]);
    }
    if (lane < 2) s0 += dot4(w4[256 + lane], x4[256 + lane]);
    return (s0 + s1) + (s2 + s3);
}

// ---- cp.async chunk machinery (shared by k_scores / k_out) ----
#define CHUNK_F4  129           // float4 per 2064-B chunk
#define PIPE_BLOCKS 296         // one wave, 2 CTA/SM
#define PIPE_WARPS  (PIPE_BLOCKS * 8)   // 2368

__device__ __forceinline__ float chunk_dot_129(const float4* __restrict__ b4,
                                               const float4* __restrict__ x4, int lane) {
    float s0 = 0.f, s1 = 0.f, s2 = 0.f, s3 = 0.f;
    s0 += dot4(b4[lane +  0], x4[lane +  0]);
    s1 += dot4(b4[lane + 32], x4[lane + 32]);
    s2 += dot4(b4[lane + 64], x4[lane + 64]);
    s3 += dot4(b4[lane + 96], x4[lane + 96]);
    if (lane < 1) s0 += dot4(b4[128], x4[128]);
    return (s0 + s1) + (s2 + s3);
}

// lane copies f4 slots {lane, lane+32, lane+64, lane+96} (+128 for lane 0);
// it later reads exactly those slots — no cross-lane smem dependency.
__device__ __forceinline__ void chunk_issue_129(float4* __restrict__ dst,
                                                const float4* __restrict__ src, int lane) {
    #pragma unroll
    for (int i = 0; i < 4; ++i)
        __pipeline_memcpy_async(&dst[lane + 32 * i], &src[lane + 32 * i], 16);
    if (lane == 0)
        __pipeline_memcpy_async(&dst[128], &src[128], 16);
}

#define IH_BLOCKS 387   // 3096 rows / 8 warps

// ---------------- K1: gates (R2 config)
__global__ void k_gates(const int* __restrict__ word, const float* __restrict__ lctx,
                        const float* __restrict__ hprev, const float* __restrict__ emb,
                        const float* __restrict__ W_ih, const float* __restrict__ W_hh,
                        const float* __restrict__ b_ih, const float* __restrict__ b_hh) {
    __shared__ __align__(16) float sx[INW];
    int lane = threadIdx.x & 31;
    int wib  = threadIdx.x >> 5;
    if (blockIdx.x < IH_BLOCKS) {
        const float* erow = emb + (size_t)word[0] * H;
        for (int i = threadIdx.x; i < INW; i += blockDim.x)
            sx[i] = (i < H) ? erow[i] : lctx[i - H];
        __syncthreads();
        int row = blockIdx.x * 8 + wib;
        float s = row_dot_516((const float4*)(W_ih + (size_t)row * INW),
                              (const float4*)sx, lane);
        s = warp_red(s);
        if (lane == 0) g_gx[row] = s + b_ih[row];
    } else {
        for (int i = threadIdx.x; i < H; i += blockDim.x) sx[i] = hprev[i];
        __syncthreads();
        int row = (blockIdx.x - IH_BLOCKS) * 8 + wib;
        float s = row_dot_258((const float4*)(W_hh + (size_t)row * H),
                              (const float4*)sx, lane);
        s = warp_red(s);
        if (lane == 0) g_gh[row] = s + b_hh[row];
    }
}

// ---------------- K2: GRU combine -> h_new; zero accumulators; c0 = b_a . h_new
__global__ void k_gru(const float* __restrict__ hprev, const float* __restrict__ b_a,
                      float* __restrict__ d_out) {
    __shared__ float acc;
    int tid = threadIdx.x;
    if (tid == 0) acc = 0.f;
    __syncthreads();
    float part = 0.f;
    for (int i = tid; i < H; i += blockDim.x) {
        float r = 1.f / (1.f + expf(-(g_gx[i] + g_gh[i])));
        float z = 1.f / (1.f + expf(-(g_gx[i + H] + g_gh[i + H])));
        float n = tanhf(g_gx[i + 2 * H] + r * g_gh[i + 2 * H]);
        float h = hprev[i];
        float hn = (1.f - z) * n + z * h;
        g_hnew[i] = hn;
        d_out[OUT_HID + i] = hn;
        g_v[i] = 0.f;
        g_ctx[i] = 0.f;
        part += b_a[i] * hn;
    }
    part = warp_red(part);
    if ((tid & 31) == 0) atomicAdd(&acc, part);
    __syncthreads();
    if (tid == 0) g_c0 = acc;
}

// ---------------- K3: v = W_a^T h_new
__global__ void k_va(const float* __restrict__ W_a) {
    int k = blockIdx.x * 128 + threadIdx.x;
    int j0 = blockIdx.y * 129;
    if (k >= H) return;
    float p0 = 0.f, p1 = 0.f, p2 = 0.f;
    int j = j0;
    #pragma unroll 3
    for (int u = 0; u < 43; ++u, j += 3) {
        p0 += W_a[(size_t)(j + 0) * H + k] * g_hnew[j + 0];
        p1 += W_a[(size_t)(j + 1) * H + k] * g_hnew[j + 1];
        p2 += W_a[(size_t)(j + 2) * H + k] * g_hnew[j + 2];
    }
    atomicAdd(&g_v[k], p0 + p1 + p2);
}

// ---------------- K4: scores via cp.async pipeline (enc row = 2 chunks)
#define SC_NITER 4   // 2368 warps * 4 rows >= 8192
__global__ __launch_bounds__(256) void k_scores(const float* __restrict__ enc) {
    __shared__ __align__(16) float sv[H];                   // 4128 B
    __shared__ __align__(16) float4 bufs[8][2][CHUNK_F4];   // 33024 B
    int tid = threadIdx.x, lane = tid & 31, wib = tid >> 5;
    for (int i = tid; i < H; i += 256) sv[i] = g_v[i];
    __syncthreads();

    const int warp_id = blockIdx.x * 8 + wib;

    #define SC_ISSUE(k_) do {                                                      \
        int _k = (k_);                                                             \
        int _j = _k >> 1; int _row = warp_id + PIPE_WARPS * _j; int _h = _k & 1;   \
        if (_j < SC_NITER && _row < SL)                                            \
            chunk_issue_129(bufs[wib][_k & 1],                                     \
                            (const float4*)(enc + (size_t)_row * H) + _h * CHUNK_F4, lane); \
        __pipeline_commit();                                                       \
    } while (0)

    SC_ISSUE(0);
    SC_ISSUE(1);
    float acc = 0.f;
    for (int k = 0; k < 2 * SC_NITER; ++k) {
        __pipeline_wait_prior(1);
        int j = k >> 1; int row = warp_id + PIPE_WARPS * j; int h = k & 1;
        if (row < SL)
            acc += chunk_dot_129(bufs[wib][k & 1],
                                 (const float4*)sv + h * CHUNK_F4, lane);
        SC_ISSUE(k + 2);
        if (h == 1) {
            float s = warp_red(acc);
            if (lane == 0 && row < SL) g_scores[row] = s + g_c0;
            acc = 0.f;
        }
    }
    #undef SC_ISSUE
}

// ---------------- K5: softmax over 8192 scores -> attn_w in d_out
__global__ void k_softmax(float* __restrict__ d_out) {
    __shared__ float red[32];
    int tid = threadIdx.x;
    float vals[8];
    float m = -1e30f;
    #pragma unroll
    for (int u = 0; u < 8; u++) { vals[u] = g_scores[tid + u * 1024]; m = fmaxf(m, vals[u]); }
    #pragma unroll
    for (int o = 16; o; o >>= 1) m = fmaxf(m, __shfl_xor_sync(0xffffffffu, m, o));
    if ((tid & 31) == 0) red[tid >> 5] = m;
    __syncthreads();
    if (tid < 32) {
        float t = red[tid];
        #pragma unroll
        for (int o = 16; o; o >>= 1) t = fmaxf(t, __shfl_xor_sync(0xffffffffu, t, o));
        if (tid == 0) red[0] = t;
    }
    __syncthreads();
    m = red[0];
    __syncthreads();
    float ssum = 0.f;
    #pragma unroll
    for (int u = 0; u < 8; u++) { vals[u] = expf(vals[u] - m); ssum += vals[u]; }
    ssum = warp_red(ssum);
    if ((tid & 31) == 0) red[tid >> 5] = ssum;
    __syncthreads();
    if (tid < 32) {
        float t = red[tid];
        t = warp_red(t);
        if (tid == 0) red[0] = t;
    }
    __syncthreads();
    float inv = 1.f / red[0];
    #pragma unroll
    for (int u = 0; u < 8; u++)
        d_out[OUT_ATTNW + tid + u * 1024] = vals[u] * inv;
}

// ---------------- K6: context[j] = sum_s w[s] * enc[s][j]  (R2 config)
__global__ void k_context(const float* __restrict__ enc, const float* __restrict__ d_out) {
    int s0 = blockIdx.x * 64;
    int tid = threadIdx.x;
    float a0 = 0, a1 = 0, a2 = 0, a3 = 0, a4 = 0;
    for (int s = s0; s < s0 + 64; ++s) {
        float w = __ldg(&d_out[OUT_ATTNW + s]);
        const float* row = enc + (size_t)s * H;
        a0 += w * row[tid];
        a1 += w * row[tid + 256];
        a2 += w * row[tid + 512];
        a3 += w * row[tid + 768];
        if (tid < 8) a4 += w * row[tid + 1024];
    }
    atomicAdd(&g_ctx[tid], a0);
    atomicAdd(&g_ctx[tid + 256], a1);
    atomicAdd(&g_ctx[tid + 512], a2);
    atomicAdd(&g_ctx[tid + 768], a3);
    if (tid < 8) atomicAdd(&g_ctx[tid + 1024], a4);
}

// ---------------- K7: logits via cp.async pipeline (W_out row = 4 chunks; join fused)
#define KO_NITER 22   // 2368 warps * 22 rows >= 50257
__global__ __launch_bounds__(256) void k_out(const float* __restrict__ W_out,
                                             const float* __restrict__ b_out,
                                             float* __restrict__ d_out) {
    __shared__ __align__(16) float sj[INW];                 // 8256 B
    __shared__ __align__(16) float4 bufs[8][2][CHUNK_F4];   // 33024 B
    int tid = threadIdx.x, lane = tid & 31, wib = tid >> 5;
    for (int i = tid; i < H; i += 256) {
        sj[i] = g_hnew[i];
        float c = g_ctx[i];
        sj[H + i] = c;
        if (blockIdx.x == 0) d_out[OUT_CTX + i] = c;
    }
    __syncthreads();

    const int warp_id = blockIdx.x * 8 + wib;

    #define KO_ISSUE(k_) do {                                                      \
        int _k = (k_);                                                             \
        int _j = _k >> 2; int _row = warp_id + PIPE_WARPS * _j; int _q = _k & 3;   \
        if (_j < KO_NITER && _row < V)                                             \
            chunk_issue_129(bufs[wib][_k & 1],                                     \
                            (const float4*)(W_out + (size_t)_row * INW) + _q * CHUNK_F4, lane); \
        __pipeline_commit();                                                       \
    } while (0)

    KO_ISSUE(0);
    KO_ISSUE(1);
    float acc = 0.f;
    for (int k = 0; k < 4 * KO_NITER; ++k) {
        __pipeline_wait_prior(1);
        int j = k >> 2; int row = warp_id + PIPE_WARPS * j; int q = k & 3;
        if (row < V)
            acc += chunk_dot_129(bufs[wib][k & 1],
                                 (const float4*)sj + q * CHUNK_F4, lane);
        KO_ISSUE(k + 2);
        if (q == 3) {
            float s = warp_red(acc);
            if (lane == 0 && row < V) d_out[row] = s + b_out[row];
            acc = 0.f;
        }
    }
    #undef KO_ISSUE
}

// ---------------- K8: log-softmax in place
__global__ void k_lsefinal(float* __restrict__ d_out) {
    __shared__ float red[32];
    __shared__ float s_lse;
    int tid = threadIdx.x;                    // 1024
    float m = -1e30f;
    for (int i = tid; i < V; i += 1024) m = fmaxf(m, d_out[i]);
    #pragma unroll
    for (int o = 16; o; o >>= 1) m = fmaxf(m, __shfl_xor_sync(0xffffffffu, m, o));
    if ((tid & 31) == 0) red[tid >> 5] = m;
    __syncthreads();
    if (tid < 32) {
        float t = red[tid];
        #pragma unroll
        for (int o = 16; o; o >>= 1) t = fmaxf(t, __shfl_xor_sync(0xffffffffu, t, o));
        if (tid == 0) red[0] = t;
    }
    __syncthreads();
    m = red[0];
    __syncthreads();
    float sum = 0.f;
    for (int i = tid; i < V; i += 1024) sum += expf(d_out[i] - m);
    sum = warp_red(sum);
    if ((tid & 31) == 0) red[tid >> 5] = sum;
    __syncthreads();
    if (tid < 32) {
        float t = red[tid];
        t = warp_red(t);
        if (tid == 0) s_lse = m + logf(t);
    }
    __syncthreads();
    float lse = s_lse;
    for (int i = tid; i < V; i += 1024) d_out[i] -= lse;
}

extern "C" void kernel_launch(void* const* d_in, const int* in_sizes, int n_in,
                              void* d_out, int out_size) {
    const int*   word  = (const int*)  d_in[0];
    const float* lctx  = (const float*)d_in[1];
    const float* hprev = (const float*)d_in[2];
    const float* enc   = (const float*)d_in[3];
    const float* emb   = (const float*)d_in[4];
    const float* W_ih  = (const float*)d_in[5];
    const float* W_hh  = (const float*)d_in[6];
    const float* b_ih  = (const float*)d_in[7];
    const float* b_hh  = (const float*)d_in[8];
    const float* W_a   = (const float*)d_in[9];
    const float* b_a   = (const float*)d_in[10];
    const float* W_out = (const float*)d_in[11];
    const float* b_out = (const float*)d_in[12];
    float* out = (float*)d_out;

    k_gates   <<<2 * IH_BLOCKS, 256>>>(word, lctx, hprev, emb, W_ih, W_hh, b_ih, b_hh);
    k_gru     <<<1, 1024>>>(hprev, b_a, out);
    k_va      <<<dim3(9, 8), 128>>>(W_a);
    k_scores  <<<PIPE_BLOCKS, 256>>>(enc);
    k_softmax <<<1, 1024>>>(out);
    k_context <<<128, 256>>>(enc, out);
    k_out     <<<PIPE_BLOCKS, 256>>>(W_out, b_out, out);
    k_lsefinal<<<1, 1024>>>(out);
}